// round 8
// baseline (speedup 1.0000x reference)
#include <cuda_runtime.h>
#include <cuda_bf16.h>
#include <math.h>

#define NB 8
#define NS 500
#define NU 128
#define NG 5
#define NC 100
#define NF 20
#define NH 5
#define GH 4
#define GD 32

typedef unsigned long long ull;

// ---------------- packed f32x2 helpers (sm_100+) ----------------
__device__ __forceinline__ ull pk2(float a, float b) {
    ull r; asm("mov.b64 %0,{%1,%2};" : "=l"(r) : "f"(a), "f"(b)); return r;
}
__device__ __forceinline__ void up2(float& a, float& b, ull p) {
    asm("mov.b64 {%0,%1},%2;" : "=f"(a), "=f"(b) : "l"(p));
}
__device__ __forceinline__ ull fma2(ull a, ull b, ull c) {
    ull d; asm("fma.rn.f32x2 %0,%1,%2,%3;" : "=l"(d) : "l"(a), "l"(b), "l"(c)); return d;
}
__device__ __forceinline__ ull mul2(ull a, ull b) {
    ull d; asm("mul.rn.f32x2 %0,%1,%2;" : "=l"(d) : "l"(a), "l"(b)); return d;
}
__device__ __forceinline__ ull add2(ull a, ull b) {
    ull d; asm("add.rn.f32x2 %0,%1,%2;" : "=l"(d) : "l"(a), "l"(b)); return d;
}
__device__ __forceinline__ float ex2f_(float x) {
    float y; asm("ex2.approx.ftz.f32 %0,%1;" : "=f"(y) : "f"(x)); return y;
}
__device__ __forceinline__ float rcpf_(float x) {
    float y; asm("rcp.approx.ftz.f32 %0,%1;" : "=f"(y) : "f"(x)); return y;
}

// ---------------- cp.async helpers ----------------
__device__ __forceinline__ unsigned s2u(const void* p) {
    return (unsigned)__cvta_generic_to_shared(p);
}
__device__ __forceinline__ void cpa16(unsigned dst, const void* src) {
    asm volatile("cp.async.cg.shared.global [%0], [%1], 16;\n" :: "r"(dst), "l"(src));
}
__device__ __forceinline__ void cpa_commit() { asm volatile("cp.async.commit_group;\n" ::); }
template <int N>
__device__ __forceinline__ void cpa_wait() { asm volatile("cp.async.wait_group %0;\n" :: "n"(N)); }

#define LOG2E 1.4426950408889634f

// scratch (device globals)
__device__ float o_scr[NB * NC * 10 * NU];    // [B,C,j,U] per-head attn outputs
__device__ float gq_scr[NB * GH * NC * GD];
__device__ float gk_scr[NB * GH * NC * GD];
__device__ float gv_scr[NB * GH * NC * GD];

// ---------------------------------------------------------------------------
// Kernel 1a: per-(b,c,h) attention head. grid = 4000, block = 32 threads,
// 4 u per thread; exp: lane 0 -> FMA-pipe poly, lanes 1-3 -> MUFU ex2
// (balances FMA vs MUFU demand: ~3752 vs ~3072 SMSP-cyc per warp).
// ---------------------------------------------------------------------------
__global__ __launch_bounds__(32, 14) void k1a_head_attn(
    const float* __restrict__ x,
    const float* __restrict__ wq, const float* __restrict__ bq,
    const float* __restrict__ wk, const float* __restrict__ bk,
    const float* __restrict__ wv, const float* __restrict__ bv)
{
    const int bid = blockIdx.x;
    const int bc = bid / NH;
    const int h = bid - bc * NH;
    const int b = bc / NC;
    const int c = bc - b * NC;
    const int t = threadIdx.x;

    __shared__ __align__(16) ull wqp[NF], wkp[NF], wvp[NF];
    __shared__ float bqs[2], bks[2], bvs[2];
    __shared__ __align__(16) float ks0[NU], ks1[NU], vs0[NU], vs1[NU];

    if (t < NF) {
        const int base = c * 200 + t * 10 + 2 * h;
        wqp[t] = *(const ull*)(wq + base);
        wkp[t] = *(const ull*)(wk + base);
        wvp[t] = *(const ull*)(wv + base);
    }
    if (t < 2) {
        bqs[t] = bq[c * 10 + 2 * h + t];
        bks[t] = bk[c * 10 + 2 * h + t];
        bvs[t] = bv[c * 10 + 2 * h + t];
    }

    float xv[4][NG];
    const float* xp = x + ((size_t)b * NS + (size_t)c * NG) * NU;
#pragma unroll
    for (int uu = 0; uu < 4; uu++) {
        const int u = t + uu * 32;
#pragma unroll
        for (int k = 0; k < NG; k++) xv[uu][k] = xp[k * NU + u];
    }
    __syncthreads();

    const int PI[10] = {0, 0, 0, 0, 1, 1, 1, 2, 2, 3};
    const int PJ[10] = {1, 2, 3, 4, 2, 3, 4, 3, 4, 4};

    float q0a[4], q1a[4];
#pragma unroll
    for (int uu = 0; uu < 4; uu++) {
        const int u = t + uu * 32;
        ull aq = pk2(bqs[0], bqs[1]);
        ull ak = pk2(bks[0], bks[1]);
        ull av = pk2(bvs[0], bvs[1]);
#pragma unroll
        for (int m = 0; m < 10; m++) {
            const ull h0 = pk2(xv[uu][PI[m]], xv[uu][PI[m]]);
            const ull h1 = pk2(xv[uu][PJ[m]], xv[uu][PJ[m]]);
            aq = fma2(h0, wqp[2 * m], aq);
            ak = fma2(h0, wkp[2 * m], ak);
            av = fma2(h0, wvp[2 * m], av);
            aq = fma2(h1, wqp[2 * m + 1], aq);
            ak = fma2(h1, wkp[2 * m + 1], ak);
            av = fma2(h1, wvp[2 * m + 1], av);
        }
        // lane 0: natural-e poly; lanes 1-3: ex2 with log2e folded
        const float QS = (uu < 1) ? 0.7071067811865476f
                                  : 0.7071067811865476f * LOG2E;
        float lo, hi;
        up2(lo, hi, aq); q0a[uu] = lo * QS; q1a[uu] = hi * QS;
        up2(lo, hi, ak); ks0[u] = lo; ks1[u] = hi;
        up2(lo, hi, av); vs0[u] = lo; vs1[u] = hi;
    }
    __syncthreads();

    const ulonglong2* __restrict__ k0p = (const ulonglong2*)ks0;
    const ulonglong2* __restrict__ k1p = (const ulonglong2*)ks1;
    const ulonglong2* __restrict__ v0p = (const ulonglong2*)vs0;
    const ulonglong2* __restrict__ v1p = (const ulonglong2*)vs1;

    const ull Z = pk2(0.f, 0.f);
    const ull C0 = pk2(1.f, 1.f);
    const ull C2 = pk2(0.5f, 0.5f);
    const ull C3 = pk2(1.f / 6.f, 1.f / 6.f);
    const ull C4 = pk2(1.f / 24.f, 1.f / 24.f);

    ull q0p[4], q1p[4];
#pragma unroll
    for (int uu = 0; uu < 4; uu++) {
        q0p[uu] = pk2(q0a[uu], q0a[uu]);
        q1p[uu] = pk2(q1a[uu], q1a[uu]);
    }
    // merged denominator accumulator (1 ull per u) + 4 output accumulators
    ull L[4], O00[4], O01[4], O10[4], O11[4];
#pragma unroll
    for (int uu = 0; uu < 4; uu++) {
        L[uu] = O00[uu] = O01[uu] = O10[uu] = O11[uu] = Z;
    }

#pragma unroll 2
    for (int i = 0; i < 32; i++) {
        const ulonglong2 K0 = k0p[i], K1 = k1p[i];
        const ulonglong2 V0 = v0p[i], V1 = v1p[i];
#pragma unroll
        for (int uu = 0; uu < 4; uu++) {
            ull s0 = fma2(q0p[uu], K0.x, mul2(q1p[uu], K1.x));
            ull s1 = fma2(q0p[uu], K0.y, mul2(q1p[uu], K1.y));
            ull e0, e1;
            if (uu < 1) {
                ull p0 = fma2(s0, C4, C3);
                ull p1 = fma2(s1, C4, C3);
                p0 = fma2(s0, p0, C2);
                p1 = fma2(s1, p1, C2);
                p0 = fma2(s0, p0, C0);
                p1 = fma2(s1, p1, C0);
                e0 = fma2(s0, p0, C0);
                e1 = fma2(s1, p1, C0);
            } else {
                float a0, a1, a2, a3;
                up2(a0, a1, s0); up2(a2, a3, s1);
                e0 = pk2(ex2f_(a0), ex2f_(a1));
                e1 = pk2(ex2f_(a2), ex2f_(a3));
            }
            L[uu] = add2(L[uu], add2(e0, e1));
            O00[uu] = fma2(e0, V0.x, O00[uu]);
            O01[uu] = fma2(e1, V0.y, O01[uu]);
            O10[uu] = fma2(e0, V1.x, O10[uu]);
            O11[uu] = fma2(e1, V1.y, O11[uu]);
        }
    }

    float* __restrict__ o0 = o_scr + (bc * 10 + 2 * h) * NU;
    float* __restrict__ o1 = o0 + NU;
#pragma unroll
    for (int uu = 0; uu < 4; uu++) {
        const int u = t + uu * 32;
        float x0, x1, x2, x3;
        up2(x0, x1, L[uu]);
        const float inv = rcpf_(x0 + x1);
        up2(x0, x1, O00[uu]); up2(x2, x3, O01[uu]);
        o0[u] = ((x0 + x1) + (x2 + x3)) * inv;
        up2(x0, x1, O10[uu]); up2(x2, x3, O11[uu]);
        o1[u] = ((x0 + x1) + (x2 + x3)) * inv;
    }
}

// ---------------------------------------------------------------------------
// Kernel 12 (fused chunk-out + graph q/k/v proj). grid = 8*20 (5 c), 128 thr.
// ---------------------------------------------------------------------------
#define K2_CHUNK 8
#define K2_NCH (NU / K2_CHUNK)

__global__ __launch_bounds__(128) void k12_chunkout_proj(
    const float* __restrict__ x,
    const float* __restrict__ wo, const float* __restrict__ bo,
    const float* __restrict__ pos,
    const float* __restrict__ gwq, const float* __restrict__ gbq,
    const float* __restrict__ gwk, const float* __restrict__ gbk,
    const float* __restrict__ gwv, const float* __restrict__ gbv,
    float* __restrict__ out)
{
    const int bid = blockIdx.x;
    const int b = bid / 20;
    const int c0 = (bid - b * 20) * 5;
    const int t = threadIdx.x;

    __shared__ __align__(16) float bwq[2][K2_CHUNK][128];
    __shared__ __align__(16) float bwk[2][K2_CHUNK][128];
    __shared__ __align__(16) float bwv[2][K2_CHUNK][128];
    __shared__ __align__(16) float wo_s[5 * 200];
    __shared__ __align__(16) float bo_s[5 * 20];
    __shared__ __align__(16) ull gtp[128][2];
    __shared__ __align__(16) float gsc[128];

    auto fill = [&](int ch) {
        const int pb = ch & 1;
        const float4* sq = (const float4*)(gwq + ch * K2_CHUNK * 128);
        const float4* sk = (const float4*)(gwk + ch * K2_CHUNK * 128);
        const float4* sv = (const float4*)(gwv + ch * K2_CHUNK * 128);
        unsigned dq = s2u(&bwq[pb][0][0]);
        unsigned dk = s2u(&bwk[pb][0][0]);
        unsigned dv = s2u(&bwv[pb][0][0]);
        cpa16(dq + t * 16, sq + t);
        cpa16(dq + (t + 128) * 16, sq + t + 128);
        cpa16(dk + t * 16, sk + t);
        cpa16(dk + (t + 128) * 16, sk + t + 128);
        cpa16(dv + t * 16, sv + t);
        cpa16(dv + (t + 128) * 16, sv + t + 128);
    };
    fill(0);
    cpa_commit();
    fill(1);
    cpa_commit();

    // ---------------- phase A: chunk output projection -> g ----------------
    for (int i = t; i < 1000; i += 128) wo_s[i] = wo[c0 * 200 + i];
    for (int i = t; i < 100; i += 128) bo_s[i] = bo[c0 * 20 + i];
    __syncthreads();

    const int PI[10] = {0, 0, 0, 0, 1, 1, 1, 2, 2, 3};
    const int PJ[10] = {1, 2, 3, 4, 2, 3, 4, 3, 4, 4};

    float gvals[5];
#pragma unroll
    for (int cc = 0; cc < 5; cc++) {
        const int c = c0 + cc;
        const int bc = b * NC + c;
        float ov[10];
#pragma unroll
        for (int j = 0; j < 10; j++) ov[j] = o_scr[(bc * 10 + j) * NU + t];
        float xv[NG];
        const float* xp = x + ((size_t)b * NS + (size_t)c * NG) * NU;
#pragma unroll
        for (int k = 0; k < NG; k++) xv[k] = xp[k * NU + t];

        ull am[10];
#pragma unroll
        for (int p = 0; p < 10; p++)
            am[p] = pk2(bo_s[cc * 20 + 2 * p], bo_s[cc * 20 + 2 * p + 1]);
#pragma unroll
        for (int j = 0; j < 10; j++) {
            const ull op = pk2(ov[j], ov[j]);
#pragma unroll
            for (int p = 0; p < 10; p++)
                am[p] = fma2(op, *(const ull*)&wo_s[cc * 200 + j * 20 + 2 * p], am[p]);
        }
        float acc = 0.f;
#pragma unroll
        for (int p = 0; p < 10; p++) {
            float m0, m1;
            up2(m0, m1, am[p]);
            float a0 = xv[PI[p]] + m0;
            float a1 = xv[PJ[p]] + m1;
            acc += (a0 > 0.f) ? a0 : 0.3f * a0;
            acc += (a1 > 0.f) ? a1 : 0.3f * a1;
        }
        const float gval = acc * (1.0f / 20.0f) + pos[c * NU + t];
        gvals[cc] = gval;
        out[bc * NU + t] = gval;   // seed residual; k3 atomically adds g_attn
    }
    gtp[t][0] = pk2(gvals[0], gvals[1]);
    gtp[t][1] = pk2(gvals[2], gvals[3]);
    gsc[t] = gvals[4];

    // ---------------- phase B: graph q/k/v projection ----------------
    ull aq[2], ak[2], av[2];
    float aqs, aks, avs;
    {
        const float bqv = gbq[t], bkv = gbk[t], bvv = gbv[t];
        aq[0] = aq[1] = pk2(bqv, bqv);
        ak[0] = ak[1] = pk2(bkv, bkv);
        av[0] = av[1] = pk2(bvv, bvv);
        aqs = bqv; aks = bkv; avs = bvv;
    }

    for (int ch = 0; ch < K2_NCH; ch++) {
        // final chunk: drain fully (its own group is the only one pending)
        if (ch + 1 < K2_NCH) { cpa_wait<1>(); } else { cpa_wait<0>(); }
        __syncthreads();
        const int pb = ch & 1;
#pragma unroll
        for (int uu = 0; uu < K2_CHUNK; uu++) {
            const int u = ch * K2_CHUNK + uu;
            const float wqv = bwq[pb][uu][t];
            const float wkv = bwk[pb][uu][t];
            const float wvv = bwv[pb][uu][t];
            const ull wq2 = pk2(wqv, wqv);
            const ull wk2 = pk2(wkv, wkv);
            const ull wv2 = pk2(wvv, wvv);
            const float gg = gsc[u];
#pragma unroll
            for (int p = 0; p < 2; p++) {
                const ull gp = gtp[u][p];
                aq[p] = fma2(wq2, gp, aq[p]);
                ak[p] = fma2(wk2, gp, ak[p]);
                av[p] = fma2(wv2, gp, av[p]);
            }
            aqs = fmaf(wqv, gg, aqs);
            aks = fmaf(wkv, gg, aks);
            avs = fmaf(wvv, gg, avs);
        }
        __syncthreads();
        if (ch + 2 < K2_NCH) {
            fill(ch + 2);
            cpa_commit();
        }
    }

    const float QS = 0.17677669529663687f * LOG2E;
    const int h = t >> 5, d = t & 31;
    const int rowbase = (b * GH + h) * NC;
#pragma unroll
    for (int p = 0; p < 2; p++) {
        float lo, hi;
        up2(lo, hi, aq[p]);
        gq_scr[(rowbase + c0 + 2 * p) * GD + d] = lo * QS;
        gq_scr[(rowbase + c0 + 2 * p + 1) * GD + d] = hi * QS;
        up2(lo, hi, ak[p]);
        gk_scr[(rowbase + c0 + 2 * p) * GD + d] = lo;
        gk_scr[(rowbase + c0 + 2 * p + 1) * GD + d] = hi;
        up2(lo, hi, av[p]);
        gv_scr[(rowbase + c0 + 2 * p) * GD + d] = lo;
        gv_scr[(rowbase + c0 + 2 * p + 1) * GD + d] = hi;
    }
    gq_scr[(rowbase + c0 + 4) * GD + d] = aqs * QS;
    gk_scr[(rowbase + c0 + 4) * GD + d] = aks;
    gv_scr[(rowbase + c0 + 4) * GD + d] = avs;
}

// ---------------------------------------------------------------------------
// Kernel 3 (graph attn + out-proj): block = ((b*GH+h)*20 + qt5), 160 thr.
// ---------------------------------------------------------------------------
#define QT 5

__global__ __launch_bounds__(160) void k3_graph_attn_out(
    const float* __restrict__ gwo, const float* __restrict__ gbo,
    float* __restrict__ out)
{
    const int bid = blockIdx.x;
    const int bh = bid / 20;
    const int qt = (bid - bh * 20) * QT;
    const int b = bh >> 2;
    const int h = bh & 3;
    const int t = threadIdx.x;

    __shared__ float qs[QT * GD];
    __shared__ float gkt[GD * 101];      // padded rows (101) -> conflict-free
    __shared__ float gv_s[NC * GD];
    __shared__ float sc[QT * NC];
    __shared__ float o_s[QT][GD];
    __shared__ float linv[QT];

    float wcol[GD];
    if (t < 128) {
#pragma unroll
        for (int d = 0; d < GD; d++)
            wcol[d] = gwo[(h * GD + d) * NU + t];
    }

    const float* __restrict__ gq_g = gq_scr + (bh * NC + qt) * GD;
    const float* __restrict__ gk_g = gk_scr + bh * NC * GD;
    const float* __restrict__ gv_g = gv_scr + bh * NC * GD;

    for (int i = t; i < QT * GD; i += 160) qs[i] = gq_g[i];
    for (int i = t; i < NC * GD; i += 160) {
        gv_s[i] = gv_g[i];
        const int cq = i >> 5, d = i & 31;
        gkt[d * 101 + cq] = gk_g[i];
    }
    __syncthreads();

    // e = exp2(q.k)
    for (int i = t; i < QT * NC; i += 160) {
        const int q = i / NC, k = i - q * NC;
        float s = 0.f;
#pragma unroll
        for (int d = 0; d < GD; d++)
            s = fmaf(qs[q * GD + d], gkt[d * 101 + k], s);
        sc[i] = ex2f_(s);
    }
    __syncthreads();

    // row sums: warp w = row w
    {
        const int q = t >> 5, l = t & 31;
        float s = sc[q * NC + l] + sc[q * NC + l + 32] + sc[q * NC + l + 64];
        if (l < 4) s += sc[q * NC + l + 96];
        s += __shfl_xor_sync(0xffffffffu, s, 16);
        s += __shfl_xor_sync(0xffffffffu, s, 8);
        s += __shfl_xor_sync(0xffffffffu, s, 4);
        s += __shfl_xor_sync(0xffffffffu, s, 2);
        s += __shfl_xor_sync(0xffffffffu, s, 1);
        if (l == 0) linv[q] = rcpf_(s);
    }
    __syncthreads();

    // o[q,d]: one output per thread (warp = q, lane = d)
    {
        const int q = t >> 5, d = t & 31;
        float acc = 0.f;
#pragma unroll 4
        for (int k = 0; k < NC; k++)
            acc = fmaf(sc[q * NC + k], gv_s[k * GD + d], acc);
        o_s[q][d] = acc * linv[q];
    }
    __syncthreads();

    // out[b, qt+q, t] += sum_d o[q,d] * wcol[d]  (+gbo once, via h==0)
    if (t < 128) {
        const float bias = (h == 0) ? gbo[t] : 0.f;
#pragma unroll
        for (int q = 0; q < QT; q++) {
            float acc = bias;
#pragma unroll
            for (int d = 0; d < GD; d++)
                acc = fmaf(o_s[q][d], wcol[d], acc);
            atomicAdd(&out[(b * NC + qt + q) * NU + t], acc);
        }
    }
}

// ---------------------------------------------------------------------------
extern "C" void kernel_launch(void* const* d_in, const int* in_sizes, int n_in,
                              void* d_out, int out_size)
{
    const float* x   = (const float*)d_in[0];
    const float* wq  = (const float*)d_in[1];
    const float* bq  = (const float*)d_in[2];
    const float* wk  = (const float*)d_in[3];
    const float* bk  = (const float*)d_in[4];
    const float* wv  = (const float*)d_in[5];
    const float* bv  = (const float*)d_in[6];
    const float* wo  = (const float*)d_in[7];
    const float* bo  = (const float*)d_in[8];
    const float* pos = (const float*)d_in[9];
    const float* gwq = (const float*)d_in[10];
    const float* gbq = (const float*)d_in[11];
    const float* gwk = (const float*)d_in[12];
    const float* gbk = (const float*)d_in[13];
    const float* gwv = (const float*)d_in[14];
    const float* gbv = (const float*)d_in[15];
    const float* gwo = (const float*)d_in[16];
    const float* gbo = (const float*)d_in[17];
    float* out = (float*)d_out;

    k1a_head_attn<<<NB * NC * NH, 32>>>(x, wq, bq, wk, bk, wv, bv);
    k12_chunkout_proj<<<NB * 20, 128>>>(x, wo, bo, pos,
                                        gwq, gbq, gwk, gbk, gwv, gbv, out);
    k3_graph_attn_out<<<NB * GH * 20, 160>>>(gwo, gbo, out);
}